// round 2
// baseline (speedup 1.0000x reference)
#include <cuda_runtime.h>

// DynamicFilterLayer2D: out[b,c,h,w] = sum_{i,j in 3x3} xpad[b,c,h+i,w+j] * f[b,c,i*3+j,h,w]
// B=8, C=32, H=256, W=256, K=3, zero pad 1.
// Traffic floor: 604MB filters (read once) + 67MB x + 67MB out = 738MB.
// R1 hit the floor at 7.05 TB/s (88% of spec). R2: 8 px/thread for 2x MLP,
// streaming hints (__ldcs/__stcs) on single-use filter reads and out writes.

static constexpr int B = 8;
static constexpr int C = 32;
static constexpr int H = 256;
static constexpr int W = 256;
static constexpr int HW = H * W;
static constexpr int W8 = W / 8;   // 32 groups of 8 pixels per row

__global__ __launch_bounds__(256)
void dynamic_filter_kernel(const float* __restrict__ x,
                           const float* __restrict__ f,
                           float* __restrict__ out)
{
    int tid = blockIdx.x * blockDim.x + threadIdx.x;
    // total threads = B*C*H*W8 = 2,097,152
    int w8 = tid & (W8 - 1);
    int t = tid >> 5;          // W8 = 32
    int h = t & (H - 1);
    int bc = t >> 8;           // H = 256

    const int w0 = w8 * 8;
    const long xbase = (long)bc * HW;
    const long fbase = (long)bc * 9 * HW;

    float acc[8];
    #pragma unroll
    for (int k = 0; k < 8; k++) acc[k] = 0.f;

    #pragma unroll
    for (int i = 0; i < 3; i++) {
        const int hr = h + i - 1;
        if (hr < 0 || hr >= H) continue;

        const float* xrow = x + xbase + (long)hr * W;
        // x values for columns w0-1 .. w0+8  → v[0..9]
        const float4 c0 = *reinterpret_cast<const float4*>(xrow + w0);
        const float4 c1 = *reinterpret_cast<const float4*>(xrow + w0 + 4);
        float v[10];
        v[0] = (w0 > 0)     ? __ldg(xrow + w0 - 1) : 0.f;
        v[1] = c0.x; v[2] = c0.y; v[3] = c0.z; v[4] = c0.w;
        v[5] = c1.x; v[6] = c1.y; v[7] = c1.z; v[8] = c1.w;
        v[9] = (w0 + 8 < W) ? __ldg(xrow + w0 + 8) : 0.f;

        const float* fp = f + fbase + (long)(i * 3) * HW + (long)h * W + w0;
        #pragma unroll
        for (int j = 0; j < 3; j++) {
            // filters: single-use → streaming loads (evict-first)
            const float4 fv0 = __ldcs(reinterpret_cast<const float4*>(fp + (long)j * HW));
            const float4 fv1 = __ldcs(reinterpret_cast<const float4*>(fp + (long)j * HW + 4));
            acc[0] = fmaf(fv0.x, v[0 + j], acc[0]);
            acc[1] = fmaf(fv0.y, v[1 + j], acc[1]);
            acc[2] = fmaf(fv0.z, v[2 + j], acc[2]);
            acc[3] = fmaf(fv0.w, v[3 + j], acc[3]);
            acc[4] = fmaf(fv1.x, v[4 + j], acc[4]);
            acc[5] = fmaf(fv1.y, v[5 + j], acc[5]);
            acc[6] = fmaf(fv1.z, v[6 + j], acc[6]);
            acc[7] = fmaf(fv1.w, v[7 + j], acc[7]);
        }
    }

    float* op = out + xbase + (long)h * W + w0;
    __stcs(reinterpret_cast<float4*>(op),     make_float4(acc[0], acc[1], acc[2], acc[3]));
    __stcs(reinterpret_cast<float4*>(op + 4), make_float4(acc[4], acc[5], acc[6], acc[7]));
}

extern "C" void kernel_launch(void* const* d_in, const int* in_sizes, int n_in,
                              void* d_out, int out_size)
{
    const float* x = (const float*)d_in[0];
    const float* f = (const float*)d_in[1];
    float* out = (float*)d_out;

    const int total = B * C * H * W8;   // 2,097,152 threads
    const int threads = 256;
    const int blocks = total / threads; // 8192
    dynamic_filter_kernel<<<blocks, threads>>>(x, f, out);
}

// round 3
// speedup vs baseline: 1.3657x; 1.3657x over previous
#include <cuda_runtime.h>

// DynamicFilterLayer2D: out[b,c,h,w] = sum_{i,j in 3x3} xpad[b,c,h+i,w+j] * f[b,c,i*3+j,h,w]
// B=8, C=32, H=256, W=256, K=3, zero pad 1.
// Traffic floor 738 MB. R1 (4px/thread, contiguous warp segments) hit 7.05 TB/s (89% DRAM busy).
// R2 (8px/thread) broke per-instruction coalescing and regressed — reverted.
// R3 = R1 layout + streaming cache hints ONLY: __ldcs on single-use filters, __stcs on out.

static constexpr int B = 8;
static constexpr int C = 32;
static constexpr int H = 256;
static constexpr int W = 256;
static constexpr int HW = H * W;
static constexpr int W4 = W / 4;

__global__ __launch_bounds__(256)
void dynamic_filter_kernel(const float* __restrict__ x,
                           const float* __restrict__ f,
                           float* __restrict__ out)
{
    int tid = blockIdx.x * blockDim.x + threadIdx.x;
    // total threads = B*C*H*W4 = 4,194,304
    int w4 = tid & (W4 - 1);
    int t = tid >> 6;          // W4 = 64
    int h = t & (H - 1);
    int bc = t >> 8;           // H = 256

    const int w0 = w4 * 4;
    const long xbase = (long)bc * HW;
    const long fbase = (long)bc * 9 * HW;

    float4 acc = make_float4(0.f, 0.f, 0.f, 0.f);

    #pragma unroll
    for (int i = 0; i < 3; i++) {
        const int hr = h + i - 1;
        if (hr < 0 || hr >= H) continue;

        const float* xrow = x + xbase + (long)hr * W;
        const float4 cen = *reinterpret_cast<const float4*>(xrow + w0);
        const float xl = (w0 > 0)     ? __ldg(xrow + w0 - 1) : 0.f;
        const float xr = (w0 + 4 < W) ? __ldg(xrow + w0 + 4) : 0.f;

        const float v0 = xl, v1 = cen.x, v2 = cen.y, v3 = cen.z, v4 = cen.w, v5 = xr;

        const float* fp = f + fbase + (long)(i * 3) * HW + (long)h * W + w0;
        {
            const float4 fv = __ldcs(reinterpret_cast<const float4*>(fp));            // j = 0
            acc.x = fmaf(fv.x, v0, acc.x);
            acc.y = fmaf(fv.y, v1, acc.y);
            acc.z = fmaf(fv.z, v2, acc.z);
            acc.w = fmaf(fv.w, v3, acc.w);
        }
        {
            const float4 fv = __ldcs(reinterpret_cast<const float4*>(fp + HW));       // j = 1
            acc.x = fmaf(fv.x, v1, acc.x);
            acc.y = fmaf(fv.y, v2, acc.y);
            acc.z = fmaf(fv.z, v3, acc.z);
            acc.w = fmaf(fv.w, v4, acc.w);
        }
        {
            const float4 fv = __ldcs(reinterpret_cast<const float4*>(fp + 2 * HW));   // j = 2
            acc.x = fmaf(fv.x, v2, acc.x);
            acc.y = fmaf(fv.y, v3, acc.y);
            acc.z = fmaf(fv.z, v4, acc.z);
            acc.w = fmaf(fv.w, v5, acc.w);
        }
    }

    __stcs(reinterpret_cast<float4*>(out + xbase + (long)h * W + w0), acc);
}

extern "C" void kernel_launch(void* const* d_in, const int* in_sizes, int n_in,
                              void* d_out, int out_size)
{
    const float* x = (const float*)d_in[0];
    const float* f = (const float*)d_in[1];
    float* out = (float*)d_out;

    const int total = B * C * H * W4;   // 4,194,304 threads
    const int threads = 256;
    const int blocks = total / threads; // 16384
    dynamic_filter_kernel<<<blocks, threads>>>(x, f, out);
}